// round 16
// baseline (speedup 1.0000x reference)
#include <cuda_runtime.h>
#include <cuda_fp16.h>
#include <math.h>

#define GS 96
#define GS2 (GS*GS)
#define NP (GS*GS*GS)          // 884736
#define NVIEW 8
#define HIM 256
#define WIM 256
#define IMPLANE (HIM*WIM)      // 65536

// Device scratch (no allocation allowed):
__device__ float4 g_latm4[NP];                   // 14.1 MB
__device__ uint2  g_imgh[NVIEW * IMPLANE];       // 4 MB, half4 (r,g,b,0)*0.5+0.5

// ---------------------------------------------------------------------------
// Kernel 0: repack images [n][3][H][W] -> half4 [n][H*W] with 0.5x+0.5
// 2 pixels per thread for ILP.
// ---------------------------------------------------------------------------
__global__ void __launch_bounds__(256) prepack_kernel(const float* __restrict__ images)
{
    int base = blockIdx.x * 512 + threadIdx.x;    // 1024 blocks
    #pragma unroll
    for (int k = 0; k < 2; k++) {
        int idx = base + k * 256;
        int n = idx >> 16;
        int o = idx & (IMPLANE - 1);
        const float* bp = images + (size_t)n * 3 * IMPLANE + o;
        float r = __ldg(bp)               * 0.5f + 0.5f;
        float g = __ldg(bp + IMPLANE)     * 0.5f + 0.5f;
        float b = __ldg(bp + 2 * IMPLANE) * 0.5f + 0.5f;
        __half2 rg = __floats2half2_rn(r, g);
        __half2 b0 = __floats2half2_rn(b, 0.f);
        uint2 u;
        u.x = *reinterpret_cast<unsigned*>(&rg);
        u.y = *reinterpret_cast<unsigned*>(&b0);
        g_imgh[idx] = u;
    }
}

__device__ __forceinline__ float3 pix2f(uint2 u)
{
    __half2 a = *reinterpret_cast<__half2*>(&u.x);
    __half2 b = *reinterpret_cast<__half2*>(&u.y);
    float2 rg = __half22float2(a);
    float2 bp = __half22float2(b);
    return make_float3(rg.x, rg.y, bp.x);
}

// ---------------------------------------------------------------------------
// Kernel A: R7/R11 winner + MLP weights in REGISTERS (loaded once, no per-view
// LDS reloads forced by the staging barriers).
// ---------------------------------------------------------------------------
__global__ void __launch_bounds__(256) encode_kernel(
    const float* __restrict__ poses,
    const float* __restrict__ focal,
    const float* __restrict__ cvec,
    const float* __restrict__ dw1, const float* __restrict__ db1,
    const float* __restrict__ dw2, const float* __restrict__ db2,
    const float* __restrict__ dw3, const float* __restrict__ db3,
    float* __restrict__ out_latent,
    float* __restrict__ lat5)
{
    __shared__ float sposes[NVIEW * 16];
    __shared__ float sf[3];
    __shared__ float s_lat5[768];

    int tid = threadIdx.x;
    if (tid < NVIEW * 16) sposes[tid] = poses[tid];
    if (tid == 128) sf[0] = focal[0] * 0.5f;
    if (tid == 129) sf[1] = cvec[0] * 0.5f;
    if (tid == 130) sf[2] = cvec[1] * 0.5f;

    // MLP weights/biases in registers (warp-uniform __ldg, L1-resident)
    float rw1[27], rb1[3], rw2[9], rb2[3], rw3[9], rb3[3];
    #pragma unroll
    for (int i = 0; i < 27; i++) rw1[i] = __ldg(dw1 + i);
    #pragma unroll
    for (int i = 0; i < 3; i++)  rb1[i] = __ldg(db1 + i);
    #pragma unroll
    for (int i = 0; i < 9; i++)  rw2[i] = __ldg(dw2 + i);
    #pragma unroll
    for (int i = 0; i < 3; i++)  rb2[i] = __ldg(db2 + i);
    #pragma unroll
    for (int i = 0; i < 9; i++)  rw3[i] = __ldg(dw3 + i);
    #pragma unroll
    for (int i = 0; i < 3; i++)  rb3[i] = __ldg(db3 + i);
    __syncthreads();

    // thread -> (ix, iy, iz) cubic tile
    int lane = tid & 31, w = tid >> 5;
    int lz = lane & 3, ly = (lane >> 2) & 3, lx = lane >> 4;   // 2x4x4
    int wx = w & 1, wy = (w >> 1) & 1, wz = w >> 2;            // 2x2x2
    int bx = blockIdx.x;                  // 3456 = 24(tx) * 12(ty) * 12(tz)
    int tz = bx % 12;
    int ty = (bx / 12) % 12;
    int tx = bx / 144;
    int jx = wx * 2 + lx;                 // 0..3
    int jy = wy * 4 + ly;                 // 0..7
    int jz = wz * 4 + lz;                 // 0..7
    int ix = tx * 4 + jx;
    int iy = ty * 8 + jy;
    int iz = tz * 8 + jz;
    int p  = (ix * GS + iy) * GS + iz;
    int m  = (jx * 8 + jy) * 8 + jz;      // z-major in-tile index

    float wxp = -1.0f + 2.0f * (float)ix / 95.0f;
    float wyp = -1.0f + 2.0f * (float)iy / 95.0f;
    float wzp = (float)iz / 95.0f;

    const float f   = sf[0];
    const float cx2 = sf[1];
    const float cy2 = sf[2];

    float acc0 = 0.f, acc1 = 0.f, acc2 = 0.f;

    #pragma unroll 2
    for (int n = 0; n < NVIEW; n++) {
        const float* Pn = sposes + n * 16;
        float dx = wxp - Pn[3];
        float dy = wyp - Pn[7];
        float dz = wzp - Pn[11];
        float camx = dx * Pn[0] + dy * Pn[4] + dz * Pn[8];
        float camy = dx * Pn[1] + dy * Pn[5] + dz * Pn[9];
        float camz = dx * Pn[2] + dy * Pn[6] + dz * Pn[10];

        const float eps = 1e-9f;
        float ddx = dx + eps, ddy = dy + eps, ddz = dz + eps;
        float invdn = rsqrtf(ddx * ddx + ddy * ddy + ddz * ddz);
        float dirx = dx * invdn, diry = dy * invdn, dirz = dz * invdn;

        float invz = __fdividef(1.0f, camz);
        float uvx =  camx * invz * f + cx2;
        float uvy = -camy * invz * f + cy2;
        float gxn = uvx * (2.0f / 127.0f) - 1.0f;
        float gyn = uvy * (2.0f / 127.0f) - 1.0f;

        bool maskz  = camz < 0.001f;
        bool inside = (fabsf(gxn) <= 1.0f) && (fabsf(gyn) <= 1.0f) && maskz;

        float l0 = 0.f, l1 = 0.f, l2 = 0.f;
        if (inside) {
            float sx = (gxn + 1.0f) * 127.5f;
            float sy = (gyn + 1.0f) * 127.5f;
            float x0f = floorf(sx), y0f = floorf(sy);
            float fx = sx - x0f, fy = sy - y0f;
            int x0 = (int)x0f, y0 = (int)y0f;
            int x1 = min(x0 + 1, WIM - 1);
            int y1 = min(y0 + 1, HIM - 1);
            float w00 = (1.f - fx) * (1.f - fy);
            float w01 = fx * (1.f - fy);
            float w10 = (1.f - fx) * fy;
            float w11 = fx * fy;
            const uint2* base = g_imgh + (size_t)n * IMPLANE;
            float3 v00 = pix2f(__ldg(base + (y0 << 8) + x0));
            float3 v01 = pix2f(__ldg(base + (y0 << 8) + x1));
            float3 v10 = pix2f(__ldg(base + (y1 << 8) + x0));
            float3 v11 = pix2f(__ldg(base + (y1 << 8) + x1));
            l0 = v00.x * w00 + v01.x * w01 + v10.x * w10 + v11.x * w11;
            l1 = v00.y * w00 + v01.y * w01 + v10.y * w10 + v11.y * w11;
            l2 = v00.z * w00 + v01.z * w01 + v10.z * w10 + v11.z * w11;
        }

        float mz = maskz ? 1.0f : 0.0f;
        dirx *= mz; diry *= mz; dirz *= mz;

        float xin[9] = { l0, l1, l2, camx, camy, camz, dirx, diry, dirz };
        float h1[3], h2[3], h3[3];
        #pragma unroll
        for (int i = 0; i < 3; i++) {
            float s = rb1[i];
            #pragma unroll
            for (int j = 0; j < 9; j++) s += xin[j] * rw1[i * 9 + j];
            h1[i] = fmaxf(s, 0.0f);
        }
        #pragma unroll
        for (int i = 0; i < 3; i++) {
            float s = rb2[i];
            #pragma unroll
            for (int j = 0; j < 3; j++) s += h1[j] * rw2[i * 3 + j];
            h2[i] = fmaxf(s, 0.0f);
        }
        #pragma unroll
        for (int i = 0; i < 3; i++) {
            float s = rb3[i];
            #pragma unroll
            for (int j = 0; j < 3; j++) s += h2[j] * rw3[i * 3 + j];
            h3[i] = s;
        }

        // out_latent[n][c][p] — 16B-dense runs
        out_latent[((size_t)n * 3 + 0) * NP + p] = l0;
        out_latent[((size_t)n * 3 + 1) * NP + p] = l1;
        out_latent[((size_t)n * 3 + 2) * NP + p] = l2;

        // lat5[n][p][c] via smem remap -> 96B-dense runs
        s_lat5[m * 3 + 0] = h3[0];
        s_lat5[m * 3 + 1] = h3[1];
        s_lat5[m * 3 + 2] = h3[2];
        __syncthreads();
        {
            float* dstbase = lat5 + (size_t)n * NP * 3;
            #pragma unroll
            for (int k = 0; k < 3; k++) {
                int j = k * 256 + tid;          // 0..767
                int r = j / 24;                 // run = jx*8+jy
                int o = j % 24;                 // offset in 96B run
                int rjx = r >> 3, rjy = r & 7;
                size_t runbase =
                    ((size_t)((tx * 4 + rjx) * GS + (ty * 8 + rjy)) * GS + tz * 8) * 3;
                dstbase[runbase + o] = s_lat5[j];
            }
        }
        __syncthreads();

        acc0 += h3[0]; acc1 += h3[1]; acc2 += h3[2];
    }

    g_latm4[p] = make_float4(acc0 * 0.125f, acc1 * 0.125f, acc2 * 0.125f, 0.f);
}

// ---------------------------------------------------------------------------
// Kernel B: softmax aggregation (R15 winner — 4-warp split on axes 0/1).
// ---------------------------------------------------------------------------
__global__ void __launch_bounds__(256) agg_kernel(
    const float* __restrict__ ayz_w1, const float* __restrict__ ayz_b1,
    const float* __restrict__ ayz_w2, const float* __restrict__ ayz_b2,
    const float* __restrict__ axz_w1, const float* __restrict__ axz_b1,
    const float* __restrict__ axz_w2, const float* __restrict__ axz_b2,
    const float* __restrict__ axy_w1, const float* __restrict__ axy_b1,
    const float* __restrict__ axy_w2, const float* __restrict__ axy_b2,
    float* __restrict__ out)
{
    int lane = threadIdx.x & 31;
    int wib  = threadIdx.x >> 5;

    if (blockIdx.x < 288) {
        __shared__ float sm[2][4][32][5];
        int tib     = wib >> 2;
        int quarter = wib & 3;
        int task    = blockIdx.x * 2 + tib;         // 0..575
        int axis = task / 288;
        int idx  = task % 288;
        int a    = idx / 3;
        int z    = (idx % 3) * 32 + lane;

        const float* W1; const float* B1; const float* W2; const float* B2;
        if (axis == 0) { W1 = ayz_w1; B1 = ayz_b1; W2 = ayz_w2; B2 = ayz_b2; }
        else           { W1 = axz_w1; B1 = axz_b1; W2 = axz_w2; B2 = axz_b2; }

        float w1r[12], b1r[3], w2r[3], b2r;
        #pragma unroll
        for (int i = 0; i < 12; i++) w1r[i] = __ldg(W1 + i);
        #pragma unroll
        for (int i = 0; i < 3; i++)  b1r[i] = __ldg(B1 + i);
        #pragma unroll
        for (int i = 0; i < 3; i++)  w2r[i] = __ldg(W2 + i);
        b2r = __ldg(B2);

        float M = -1e30f, D = 0.f;
        float ac0 = 0.f, ac1 = 0.f, ac2 = 0.f;

        int ebeg = quarter * 24;
        #pragma unroll 1
        for (int e0 = ebeg; e0 < ebeg + 24; e0 += 4) {
            float4 mv[4]; float sc[4];
            #pragma unroll
            for (int k = 0; k < 4; k++) {
                int e = e0 + k;
                int pp = (axis == 0) ? (e * GS + a) * GS + z
                                     : (a * GS + e) * GS + z;
                mv[k] = __ldg(&g_latm4[pp]);
            }
            #pragma unroll
            for (int k = 0; k < 4; k++) {
                int e = e0 + k;
                float coord = -1.0f + 2.0f * (float)e / 95.0f;
                float s = b2r;
                #pragma unroll
                for (int i = 0; i < 3; i++) {
                    float h = w1r[i*4+0] * mv[k].x + w1r[i*4+1] * mv[k].y +
                              w1r[i*4+2] * mv[k].z + w1r[i*4+3] * coord + b1r[i];
                    s += fmaxf(h, 0.0f) * w2r[i];
                }
                sc[k] = s;
            }
            float bm = fmaxf(fmaxf(sc[0], sc[1]), fmaxf(sc[2], sc[3]));
            float Mn = fmaxf(M, bm);
            float scale = __expf(M - Mn);
            float w0 = __expf(sc[0] - Mn), w1 = __expf(sc[1] - Mn);
            float w2 = __expf(sc[2] - Mn), w3 = __expf(sc[3] - Mn);
            D   = D   * scale + (w0 + w1 + w2 + w3);
            ac0 = ac0 * scale + w0*mv[0].x + w1*mv[1].x + w2*mv[2].x + w3*mv[3].x;
            ac1 = ac1 * scale + w0*mv[0].y + w1*mv[1].y + w2*mv[2].y + w3*mv[3].y;
            ac2 = ac2 * scale + w0*mv[0].z + w1*mv[1].z + w2*mv[2].z + w3*mv[3].z;
            M = Mn;
        }

        if (quarter != 0) {
            sm[tib][quarter][lane][0] = M;
            sm[tib][quarter][lane][1] = D;
            sm[tib][quarter][lane][2] = ac0;
            sm[tib][quarter][lane][3] = ac1;
            sm[tib][quarter][lane][4] = ac2;
        }
        __syncthreads();
        if (quarter == 0) {
            #pragma unroll
            for (int q = 1; q < 4; q++) {
                float Mb = sm[tib][q][lane][0], Db = sm[tib][q][lane][1];
                float b0 = sm[tib][q][lane][2], b1 = sm[tib][q][lane][3], b2 = sm[tib][q][lane][4];
                float Mn = fmaxf(M, Mb);
                float sa = __expf(M - Mn), sb = __expf(Mb - Mn);
                D   = D   * sa + Db * sb;
                ac0 = ac0 * sa + b0 * sb;
                ac1 = ac1 * sa + b1 * sb;
                ac2 = ac2 * sa + b2 * sb;
                M = Mn;
            }
            float inv = __fdividef(1.0f, D);
            float* dst = out + (axis == 0 ? 2 * 27648 : 0);
            dst[0 * GS2 + a * GS + z] = ac0 * inv;
            dst[1 * GS2 + a * GS + z] = ac1 * inv;
            dst[2 * GS2 + a * GS + z] = ac2 * inv;
        }
    } else {
        int gw2 = (blockIdx.x - 288) * 8 + wib;   // 0..9215
        int a = gw2 / GS;
        int b = gw2 % GS;

        float w1r[12], b1r[3], w2r[3], b2r;
        #pragma unroll
        for (int i = 0; i < 12; i++) w1r[i] = __ldg(axy_w1 + i);
        #pragma unroll
        for (int i = 0; i < 3; i++)  b1r[i] = __ldg(axy_b1 + i);
        #pragma unroll
        for (int i = 0; i < 3; i++)  w2r[i] = __ldg(axy_w2 + i);
        b2r = __ldg(axy_b2);

        float lm[3][3];
        float sc[3];
        int pbase = (a * GS + b) * GS;
        #pragma unroll
        for (int k = 0; k < 3; k++) {
            int e = lane * 3 + k;
            float coord = (float)e / 95.0f;
            float4 m = __ldg(&g_latm4[pbase + e]);
            lm[k][0] = m.x; lm[k][1] = m.y; lm[k][2] = m.z;
            float s = b2r;
            #pragma unroll
            for (int i = 0; i < 3; i++) {
                float h = w1r[i*4+0] * m.x + w1r[i*4+1] * m.y +
                          w1r[i*4+2] * m.z + w1r[i*4+3] * coord + b1r[i];
                s += fmaxf(h, 0.0f) * w2r[i];
            }
            sc[k] = s;
        }

        float m = fmaxf(sc[0], fmaxf(sc[1], sc[2]));
        #pragma unroll
        for (int off = 16; off > 0; off >>= 1)
            m = fmaxf(m, __shfl_xor_sync(0xffffffffu, m, off));
        float e0 = __expf(sc[0] - m), e1 = __expf(sc[1] - m), e2 = __expf(sc[2] - m);
        float ssum = e0 + e1 + e2;
        #pragma unroll
        for (int off = 16; off > 0; off >>= 1)
            ssum += __shfl_xor_sync(0xffffffffu, ssum, off);
        float inv = __fdividef(1.0f, ssum);

        float fl[3];
        #pragma unroll
        for (int c = 0; c < 3; c++) {
            float acc = lm[0][c] * e0 + lm[1][c] * e1 + lm[2][c] * e2;
            #pragma unroll
            for (int off = 16; off > 0; off >>= 1)
                acc += __shfl_xor_sync(0xffffffffu, acc, off);
            fl[c] = acc * inv;
        }

        if (lane == 0) {
            float* dst = out + 27648;
            #pragma unroll
            for (int c = 0; c < 3; c++)
                dst[c * GS2 + a * GS + b] = fl[c];
        }
    }
}

extern "C" void kernel_launch(void* const* d_in, const int* in_sizes, int n_in,
                              void* d_out, int out_size)
{
    const float* images = (const float*)d_in[0];
    const float* poses  = (const float*)d_in[1];
    const float* focal  = (const float*)d_in[2];
    const float* cvec   = (const float*)d_in[3];
    const float* dw1 = (const float*)d_in[4];
    const float* db1 = (const float*)d_in[5];
    const float* dw2 = (const float*)d_in[6];
    const float* db2 = (const float*)d_in[7];
    const float* dw3 = (const float*)d_in[8];
    const float* db3 = (const float*)d_in[9];
    const float* ayz_w1 = (const float*)d_in[10];
    const float* ayz_b1 = (const float*)d_in[11];
    const float* ayz_w2 = (const float*)d_in[12];
    const float* ayz_b2 = (const float*)d_in[13];
    const float* axz_w1 = (const float*)d_in[14];
    const float* axz_b1 = (const float*)d_in[15];
    const float* axz_w2 = (const float*)d_in[16];
    const float* axz_b2 = (const float*)d_in[17];
    const float* axy_w1 = (const float*)d_in[18];
    const float* axy_b1 = (const float*)d_in[19];
    const float* axy_w2 = (const float*)d_in[20];
    const float* axy_b2 = (const float*)d_in[21];

    float* out = (float*)d_out;
    float* out_latent = out + 3 * 27648;
    float* lat5       = out + 3 * 27648 + (size_t)NVIEW * 3 * NP;

    prepack_kernel<<<1024, 256>>>(images);

    encode_kernel<<<3456, 256>>>(poses, focal, cvec,
                                 dw1, db1, dw2, db2, dw3, db3,
                                 out_latent, lat5);

    agg_kernel<<<1440, 256>>>(ayz_w1, ayz_b1, ayz_w2, ayz_b2,
                              axz_w1, axz_b1, axz_w2, axz_b2,
                              axy_w1, axy_b1, axy_w2, axy_b2,
                              out);
}

// round 17
// speedup vs baseline: 1.0066x; 1.0066x over previous
#include <cuda_runtime.h>
#include <cuda_fp16.h>
#include <math.h>

#define GS 96
#define GS2 (GS*GS)
#define NP (GS*GS*GS)          // 884736
#define NVIEW 8
#define HIM 256
#define WIM 256
#define IMPLANE (HIM*WIM)      // 65536

// Device scratch (no allocation allowed):
__device__ float4 g_latm4[NP];                   // 14.1 MB
__device__ uint2  g_imgh[NVIEW * IMPLANE];       // 4 MB, half4 (r,g,b,0)*0.5+0.5

// ---------------------------------------------------------------------------
// Kernel 0: repack images [n][3][H][W] -> half4 [n][H*W] with 0.5x+0.5
// ---------------------------------------------------------------------------
__global__ void __launch_bounds__(256) prepack_kernel(const float* __restrict__ images)
{
    int idx = blockIdx.x * 256 + threadIdx.x;     // 524288 total
    int n = idx >> 16;
    int o = idx & (IMPLANE - 1);
    const float* bp = images + (size_t)n * 3 * IMPLANE + o;
    float r = __ldg(bp)               * 0.5f + 0.5f;
    float g = __ldg(bp + IMPLANE)     * 0.5f + 0.5f;
    float b = __ldg(bp + 2 * IMPLANE) * 0.5f + 0.5f;
    __half2 rg = __floats2half2_rn(r, g);
    __half2 b0 = __floats2half2_rn(b, 0.f);
    uint2 u;
    u.x = *reinterpret_cast<unsigned*>(&rg);
    u.y = *reinterpret_cast<unsigned*>(&b0);
    g_imgh[idx] = u;
}

__device__ __forceinline__ float3 pix2f(uint2 u)
{
    __half2 a = *reinterpret_cast<__half2*>(&u.x);
    __half2 b = *reinterpret_cast<__half2*>(&u.y);
    float2 rg = __half22float2(a);
    float2 bp = __half22float2(b);
    return make_float3(rg.x, rg.y, bp.x);
}

// ---------------------------------------------------------------------------
// Kernel A: R15 winner + hoisted lat5 index math + double-buffered staging
// (one __syncthreads per view).
// ---------------------------------------------------------------------------
__global__ void __launch_bounds__(256) encode_kernel(
    const float* __restrict__ poses,
    const float* __restrict__ focal,
    const float* __restrict__ cvec,
    const float* __restrict__ dw1, const float* __restrict__ db1,
    const float* __restrict__ dw2, const float* __restrict__ db2,
    const float* __restrict__ dw3, const float* __restrict__ db3,
    float* __restrict__ out_latent,
    float* __restrict__ lat5)
{
    __shared__ float sposes[NVIEW * 16];
    __shared__ float sw1[27], sb1[3], sw2[9], sb2[3], sw3[9], sb3[3];
    __shared__ float sf[3];
    __shared__ float s_lat5[2][768];

    int tid = threadIdx.x;
    if (tid < NVIEW * 16) sposes[tid] = poses[tid];
    if (tid >= 128 && tid < 128 + 27) sw1[tid - 128] = dw1[tid - 128];
    int u = tid - 160;
    if (u >= 0 && u < 3)  sb1[u] = db1[u];
    if (u >= 3 && u < 12) sw2[u - 3] = dw2[u - 3];
    if (u >= 12 && u < 15) sb2[u - 12] = db2[u - 12];
    if (u >= 15 && u < 24) sw3[u - 15] = dw3[u - 15];
    if (u >= 24 && u < 27) sb3[u - 24] = db3[u - 24];
    if (u == 27) sf[0] = focal[0] * 0.5f;
    if (u == 28) sf[1] = cvec[0] * 0.5f;
    if (u == 29) sf[2] = cvec[1] * 0.5f;
    __syncthreads();

    // thread -> (ix, iy, iz) cubic tile
    int lane = tid & 31, w = tid >> 5;
    int lz = lane & 3, ly = (lane >> 2) & 3, lx = lane >> 4;   // 2x4x4
    int wx = w & 1, wy = (w >> 1) & 1, wz = w >> 2;            // 2x2x2
    int bx = blockIdx.x;                  // 3456 = 24(tx) * 12(ty) * 12(tz)
    int tz = bx % 12;
    int ty = (bx / 12) % 12;
    int tx = bx / 144;
    int jx = wx * 2 + lx;                 // 0..3
    int jy = wy * 4 + ly;                 // 0..7
    int jz = wz * 4 + lz;                 // 0..7
    int ix = tx * 4 + jx;
    int iy = ty * 8 + jy;
    int iz = tz * 8 + jz;
    int p  = (ix * GS + iy) * GS + iz;
    int m  = (jx * 8 + jy) * 8 + jz;      // z-major in-tile index

    // hoisted lat5 store offsets (view-invariant)
    size_t l5off[3];
    #pragma unroll
    for (int k = 0; k < 3; k++) {
        int j = k * 256 + tid;            // 0..767
        int r = j / 24;                   // run = jx*8+jy
        int o = j % 24;                   // offset in 96B run
        int rjx = r >> 3, rjy = r & 7;
        l5off[k] = ((size_t)((tx * 4 + rjx) * GS + (ty * 8 + rjy)) * GS + tz * 8) * 3 + o;
    }

    float wxp = -1.0f + 2.0f * (float)ix / 95.0f;
    float wyp = -1.0f + 2.0f * (float)iy / 95.0f;
    float wzp = (float)iz / 95.0f;

    const float f   = sf[0];
    const float cx2 = sf[1];
    const float cy2 = sf[2];

    float acc0 = 0.f, acc1 = 0.f, acc2 = 0.f;

    #pragma unroll 2
    for (int n = 0; n < NVIEW; n++) {
        const float* Pn = sposes + n * 16;
        float dx = wxp - Pn[3];
        float dy = wyp - Pn[7];
        float dz = wzp - Pn[11];
        float camx = dx * Pn[0] + dy * Pn[4] + dz * Pn[8];
        float camy = dx * Pn[1] + dy * Pn[5] + dz * Pn[9];
        float camz = dx * Pn[2] + dy * Pn[6] + dz * Pn[10];

        const float eps = 1e-9f;
        float ddx = dx + eps, ddy = dy + eps, ddz = dz + eps;
        float invdn = rsqrtf(ddx * ddx + ddy * ddy + ddz * ddz);
        float dirx = dx * invdn, diry = dy * invdn, dirz = dz * invdn;

        float invz = __fdividef(1.0f, camz);
        float uvx =  camx * invz * f + cx2;
        float uvy = -camy * invz * f + cy2;
        float gxn = uvx * (2.0f / 127.0f) - 1.0f;
        float gyn = uvy * (2.0f / 127.0f) - 1.0f;

        bool maskz  = camz < 0.001f;
        bool inside = (fabsf(gxn) <= 1.0f) && (fabsf(gyn) <= 1.0f) && maskz;

        float l0 = 0.f, l1 = 0.f, l2 = 0.f;
        if (inside) {
            float sx = (gxn + 1.0f) * 127.5f;
            float sy = (gyn + 1.0f) * 127.5f;
            float x0f = floorf(sx), y0f = floorf(sy);
            float fx = sx - x0f, fy = sy - y0f;
            int x0 = (int)x0f, y0 = (int)y0f;
            int x1 = min(x0 + 1, WIM - 1);
            int y1 = min(y0 + 1, HIM - 1);
            float w00 = (1.f - fx) * (1.f - fy);
            float w01 = fx * (1.f - fy);
            float w10 = (1.f - fx) * fy;
            float w11 = fx * fy;
            const uint2* base = g_imgh + (size_t)n * IMPLANE;
            float3 v00 = pix2f(__ldg(base + (y0 << 8) + x0));
            float3 v01 = pix2f(__ldg(base + (y0 << 8) + x1));
            float3 v10 = pix2f(__ldg(base + (y1 << 8) + x0));
            float3 v11 = pix2f(__ldg(base + (y1 << 8) + x1));
            l0 = v00.x * w00 + v01.x * w01 + v10.x * w10 + v11.x * w11;
            l1 = v00.y * w00 + v01.y * w01 + v10.y * w10 + v11.y * w11;
            l2 = v00.z * w00 + v01.z * w01 + v10.z * w10 + v11.z * w11;
        }

        float mz = maskz ? 1.0f : 0.0f;
        dirx *= mz; diry *= mz; dirz *= mz;

        float xin[9] = { l0, l1, l2, camx, camy, camz, dirx, diry, dirz };
        float h1[3], h2[3], h3[3];
        #pragma unroll
        for (int i = 0; i < 3; i++) {
            float s = sb1[i];
            #pragma unroll
            for (int j = 0; j < 9; j++) s += xin[j] * sw1[i * 9 + j];
            h1[i] = fmaxf(s, 0.0f);
        }
        #pragma unroll
        for (int i = 0; i < 3; i++) {
            float s = sb2[i];
            #pragma unroll
            for (int j = 0; j < 3; j++) s += h1[j] * sw2[i * 3 + j];
            h2[i] = fmaxf(s, 0.0f);
        }
        #pragma unroll
        for (int i = 0; i < 3; i++) {
            float s = sb3[i];
            #pragma unroll
            for (int j = 0; j < 3; j++) s += h2[j] * sw3[i * 3 + j];
            h3[i] = s;
        }

        // out_latent[n][c][p] — 16B-dense runs
        out_latent[((size_t)n * 3 + 0) * NP + p] = l0;
        out_latent[((size_t)n * 3 + 1) * NP + p] = l1;
        out_latent[((size_t)n * 3 + 2) * NP + p] = l2;

        // lat5[n][p][c] via double-buffered smem remap -> 96B-dense runs
        float* S = s_lat5[n & 1];
        S[m * 3 + 0] = h3[0];
        S[m * 3 + 1] = h3[1];
        S[m * 3 + 2] = h3[2];
        __syncthreads();
        {
            float* dstbase = lat5 + (size_t)n * NP * 3;
            dstbase[l5off[0]] = S[tid];
            dstbase[l5off[1]] = S[256 + tid];
            dstbase[l5off[2]] = S[512 + tid];
        }
        // no second sync: next view writes the other buffer

        acc0 += h3[0]; acc1 += h3[1]; acc2 += h3[2];
    }

    g_latm4[p] = make_float4(acc0 * 0.125f, acc1 * 0.125f, acc2 * 0.125f, 0.f);
}

// ---------------------------------------------------------------------------
// Kernel B: softmax aggregation (R15 winner — 4-warp split on axes 0/1).
// ---------------------------------------------------------------------------
__global__ void __launch_bounds__(256) agg_kernel(
    const float* __restrict__ ayz_w1, const float* __restrict__ ayz_b1,
    const float* __restrict__ ayz_w2, const float* __restrict__ ayz_b2,
    const float* __restrict__ axz_w1, const float* __restrict__ axz_b1,
    const float* __restrict__ axz_w2, const float* __restrict__ axz_b2,
    const float* __restrict__ axy_w1, const float* __restrict__ axy_b1,
    const float* __restrict__ axy_w2, const float* __restrict__ axy_b2,
    float* __restrict__ out)
{
    int lane = threadIdx.x & 31;
    int wib  = threadIdx.x >> 5;

    if (blockIdx.x < 288) {
        __shared__ float sm[2][4][32][5];
        int tib     = wib >> 2;
        int quarter = wib & 3;
        int task    = blockIdx.x * 2 + tib;         // 0..575
        int axis = task / 288;
        int idx  = task % 288;
        int a    = idx / 3;
        int z    = (idx % 3) * 32 + lane;

        const float* W1; const float* B1; const float* W2; const float* B2;
        if (axis == 0) { W1 = ayz_w1; B1 = ayz_b1; W2 = ayz_w2; B2 = ayz_b2; }
        else           { W1 = axz_w1; B1 = axz_b1; W2 = axz_w2; B2 = axz_b2; }

        float w1r[12], b1r[3], w2r[3], b2r;
        #pragma unroll
        for (int i = 0; i < 12; i++) w1r[i] = __ldg(W1 + i);
        #pragma unroll
        for (int i = 0; i < 3; i++)  b1r[i] = __ldg(B1 + i);
        #pragma unroll
        for (int i = 0; i < 3; i++)  w2r[i] = __ldg(W2 + i);
        b2r = __ldg(B2);

        float M = -1e30f, D = 0.f;
        float ac0 = 0.f, ac1 = 0.f, ac2 = 0.f;

        int ebeg = quarter * 24;
        #pragma unroll 1
        for (int e0 = ebeg; e0 < ebeg + 24; e0 += 4) {
            float4 mv[4]; float sc[4];
            #pragma unroll
            for (int k = 0; k < 4; k++) {
                int e = e0 + k;
                int pp = (axis == 0) ? (e * GS + a) * GS + z
                                     : (a * GS + e) * GS + z;
                mv[k] = __ldg(&g_latm4[pp]);
            }
            #pragma unroll
            for (int k = 0; k < 4; k++) {
                int e = e0 + k;
                float coord = -1.0f + 2.0f * (float)e / 95.0f;
                float s = b2r;
                #pragma unroll
                for (int i = 0; i < 3; i++) {
                    float h = w1r[i*4+0] * mv[k].x + w1r[i*4+1] * mv[k].y +
                              w1r[i*4+2] * mv[k].z + w1r[i*4+3] * coord + b1r[i];
                    s += fmaxf(h, 0.0f) * w2r[i];
                }
                sc[k] = s;
            }
            float bm = fmaxf(fmaxf(sc[0], sc[1]), fmaxf(sc[2], sc[3]));
            float Mn = fmaxf(M, bm);
            float scale = __expf(M - Mn);
            float w0 = __expf(sc[0] - Mn), w1 = __expf(sc[1] - Mn);
            float w2 = __expf(sc[2] - Mn), w3 = __expf(sc[3] - Mn);
            D   = D   * scale + (w0 + w1 + w2 + w3);
            ac0 = ac0 * scale + w0*mv[0].x + w1*mv[1].x + w2*mv[2].x + w3*mv[3].x;
            ac1 = ac1 * scale + w0*mv[0].y + w1*mv[1].y + w2*mv[2].y + w3*mv[3].y;
            ac2 = ac2 * scale + w0*mv[0].z + w1*mv[1].z + w2*mv[2].z + w3*mv[3].z;
            M = Mn;
        }

        if (quarter != 0) {
            sm[tib][quarter][lane][0] = M;
            sm[tib][quarter][lane][1] = D;
            sm[tib][quarter][lane][2] = ac0;
            sm[tib][quarter][lane][3] = ac1;
            sm[tib][quarter][lane][4] = ac2;
        }
        __syncthreads();
        if (quarter == 0) {
            #pragma unroll
            for (int q = 1; q < 4; q++) {
                float Mb = sm[tib][q][lane][0], Db = sm[tib][q][lane][1];
                float b0 = sm[tib][q][lane][2], b1 = sm[tib][q][lane][3], b2 = sm[tib][q][lane][4];
                float Mn = fmaxf(M, Mb);
                float sa = __expf(M - Mn), sb = __expf(Mb - Mn);
                D   = D   * sa + Db * sb;
                ac0 = ac0 * sa + b0 * sb;
                ac1 = ac1 * sa + b1 * sb;
                ac2 = ac2 * sa + b2 * sb;
                M = Mn;
            }
            float inv = __fdividef(1.0f, D);
            float* dst = out + (axis == 0 ? 2 * 27648 : 0);
            dst[0 * GS2 + a * GS + z] = ac0 * inv;
            dst[1 * GS2 + a * GS + z] = ac1 * inv;
            dst[2 * GS2 + a * GS + z] = ac2 * inv;
        }
    } else {
        int gw2 = (blockIdx.x - 288) * 8 + wib;   // 0..9215
        int a = gw2 / GS;
        int b = gw2 % GS;

        float w1r[12], b1r[3], w2r[3], b2r;
        #pragma unroll
        for (int i = 0; i < 12; i++) w1r[i] = __ldg(axy_w1 + i);
        #pragma unroll
        for (int i = 0; i < 3; i++)  b1r[i] = __ldg(axy_b1 + i);
        #pragma unroll
        for (int i = 0; i < 3; i++)  w2r[i] = __ldg(axy_w2 + i);
        b2r = __ldg(axy_b2);

        float lm[3][3];
        float sc[3];
        int pbase = (a * GS + b) * GS;
        #pragma unroll
        for (int k = 0; k < 3; k++) {
            int e = lane * 3 + k;
            float coord = (float)e / 95.0f;
            float4 m = __ldg(&g_latm4[pbase + e]);
            lm[k][0] = m.x; lm[k][1] = m.y; lm[k][2] = m.z;
            float s = b2r;
            #pragma unroll
            for (int i = 0; i < 3; i++) {
                float h = w1r[i*4+0] * m.x + w1r[i*4+1] * m.y +
                          w1r[i*4+2] * m.z + w1r[i*4+3] * coord + b1r[i];
                s += fmaxf(h, 0.0f) * w2r[i];
            }
            sc[k] = s;
        }

        float m = fmaxf(sc[0], fmaxf(sc[1], sc[2]));
        #pragma unroll
        for (int off = 16; off > 0; off >>= 1)
            m = fmaxf(m, __shfl_xor_sync(0xffffffffu, m, off));
        float e0 = __expf(sc[0] - m), e1 = __expf(sc[1] - m), e2 = __expf(sc[2] - m);
        float ssum = e0 + e1 + e2;
        #pragma unroll
        for (int off = 16; off > 0; off >>= 1)
            ssum += __shfl_xor_sync(0xffffffffu, ssum, off);
        float inv = __fdividef(1.0f, ssum);

        float fl[3];
        #pragma unroll
        for (int c = 0; c < 3; c++) {
            float acc = lm[0][c] * e0 + lm[1][c] * e1 + lm[2][c] * e2;
            #pragma unroll
            for (int off = 16; off > 0; off >>= 1)
                acc += __shfl_xor_sync(0xffffffffu, acc, off);
            fl[c] = acc * inv;
        }

        if (lane == 0) {
            float* dst = out + 27648;
            #pragma unroll
            for (int c = 0; c < 3; c++)
                dst[c * GS2 + a * GS + b] = fl[c];
        }
    }
}

extern "C" void kernel_launch(void* const* d_in, const int* in_sizes, int n_in,
                              void* d_out, int out_size)
{
    const float* images = (const float*)d_in[0];
    const float* poses  = (const float*)d_in[1];
    const float* focal  = (const float*)d_in[2];
    const float* cvec   = (const float*)d_in[3];
    const float* dw1 = (const float*)d_in[4];
    const float* db1 = (const float*)d_in[5];
    const float* dw2 = (const float*)d_in[6];
    const float* db2 = (const float*)d_in[7];
    const float* dw3 = (const float*)d_in[8];
    const float* db3 = (const float*)d_in[9];
    const float* ayz_w1 = (const float*)d_in[10];
    const float* ayz_b1 = (const float*)d_in[11];
    const float* ayz_w2 = (const float*)d_in[12];
    const float* ayz_b2 = (const float*)d_in[13];
    const float* axz_w1 = (const float*)d_in[14];
    const float* axz_b1 = (const float*)d_in[15];
    const float* axz_w2 = (const float*)d_in[16];
    const float* axz_b2 = (const float*)d_in[17];
    const float* axy_w1 = (const float*)d_in[18];
    const float* axy_b1 = (const float*)d_in[19];
    const float* axy_w2 = (const float*)d_in[20];
    const float* axy_b2 = (const float*)d_in[21];

    float* out = (float*)d_out;
    float* out_latent = out + 3 * 27648;
    float* lat5       = out + 3 * 27648 + (size_t)NVIEW * 3 * NP;

    prepack_kernel<<<2048, 256>>>(images);

    encode_kernel<<<3456, 256>>>(poses, focal, cvec,
                                 dw1, db1, dw2, db2, dw3, db3,
                                 out_latent, lat5);

    agg_kernel<<<1440, 256>>>(ayz_w1, ayz_b1, ayz_w2, ayz_b2,
                              axz_w1, axz_b1, axz_w2, axz_b2,
                              axy_w1, axy_b1, axy_w2, axy_b2,
                              out);
}